// round 15
// baseline (speedup 1.0000x reference)
#include <cuda_runtime.h>
#include <math.h>
#include <stdint.h>

#define B_   2
#define S_   512
#define D_   512
#define H_   8
#define HD_  64
#define HID_ 512
#define FFN_ 2048
#define CC   32
#define NC   (S_/CC)
#define ROWS (B_*S_)

#define PDL_TRIGGER() asm volatile("griddepcontrol.launch_dependents;" ::: "memory")
#define PDL_WAIT()    asm volatile("griddepcontrol.wait;" ::: "memory")

// ---------------- scratch (device globals) ----------------
__device__ float g_q    [ROWS*HID_];
__device__ float g_k    [ROWS*HID_];
__device__ float g_v    [ROWS*HID_];
__device__ float g_attn [ROWS*HID_];
__device__ float g_y1   [ROWS*D_];
__device__ float g_hbuf [ROWS*FFN_];
__device__ float g_Schunk[B_*H_*NC*HD_*HD_];
__device__ float g_Sstart[B_*H_*NC*HD_*HD_];
__device__ float g_Lg     [B_*NC*CC];
__device__ float g_chunkP2[B_*NC];
__device__ float g_wdpart[4*ROWS*D_];
__device__ float g_r1   [ROWS];
__device__ float g_ssqA [ROWS];
__device__ float g_ssq2 [ROWS];
// tf32-rounded, TRANSPOSED weights with ln folded: Wt[n][k]
__device__ float g_wq[HID_*D_];
__device__ float g_wk[HID_*D_];
__device__ float g_wv[HID_*D_];
__device__ float g_wo[D_*HID_];
__device__ float g_wg[FFN_*D_];
__device__ float g_wu[FFN_*D_];
__device__ float g_wd[D_*FFN_];

// ---------------- helpers ----------------
__device__ __forceinline__ unsigned f2tf32(float x) {
    unsigned r; asm("cvt.rna.tf32.f32 %0, %1;" : "=r"(r) : "f"(x)); return r;
}
__device__ __forceinline__ float rnd32(float x) { return __uint_as_float(f2tf32(x)); }
__device__ __forceinline__ void mma_tf32(float* d, const unsigned* a, const unsigned* b) {
    asm("mma.sync.aligned.m16n8k8.row.col.f32.tf32.tf32.f32 "
        "{%0,%1,%2,%3}, {%4,%5,%6,%7}, {%8,%9}, {%0,%1,%2,%3};"
        : "+f"(d[0]), "+f"(d[1]), "+f"(d[2]), "+f"(d[3])
        : "r"(a[0]), "r"(a[1]), "r"(a[2]), "r"(a[3]), "r"(b[0]), "r"(b[1]));
}
__device__ __forceinline__ uint32_t s2u(const void* p) {
    return (uint32_t)__cvta_generic_to_shared(p);
}
__device__ __forceinline__ void cpa16(uint32_t d, const void* g) {
    asm volatile("cp.async.cg.shared.global [%0], [%1], 16;" :: "r"(d), "l"(g));
}
#define CP_COMMIT() asm volatile("cp.async.commit_group;")
__device__ __forceinline__ void ldsm4(unsigned& r0, unsigned& r1, unsigned& r2, unsigned& r3,
                                      uint32_t addr) {
    asm volatile("ldmatrix.sync.aligned.m8n8.x4.shared.b16 {%0,%1,%2,%3}, [%4];"
                 : "=r"(r0), "=r"(r1), "=r"(r2), "=r"(r3) : "r"(addr));
}

// ============================================================
// prep kernel.  block = (32, 8).  Block map as in R14.
// ============================================================
__device__ __forceinline__ void trans_tile(const float* __restrict__ W,
                                           float* __restrict__ Wt,
                                           int K, int N, int n0, int k0,
                                           const float* __restrict__ svec) {
    __shared__ float t[32][33];
    int x = threadIdx.x, y = threadIdx.y;
    #pragma unroll
    for (int i = 0; i < 32; i += 8)
        t[y+i][x] = W[(size_t)(k0+y+i)*N + n0 + x];
    __syncthreads();
    float s = svec ? svec[k0 + x] : 1.0f;
    #pragma unroll
    for (int i = 0; i < 32; i += 8)
        Wt[(size_t)(n0+y+i)*K + k0 + x] = rnd32(t[x][y+i] * s);
}
__device__ __forceinline__ void rms_r(const float* __restrict__ x,
                                      float* __restrict__ rv, int row) {
    int lane = threadIdx.x;
    const float4* xp = (const float4*)(x + (size_t)row*512);
    float ss = 0.f;
    #pragma unroll
    for (int i = 0; i < 4; i++) {
        float4 v = xp[lane + 32*i];
        ss += v.x*v.x + v.y*v.y + v.z*v.z + v.w*v.w;
    }
    #pragma unroll
    for (int o = 16; o > 0; o >>= 1) ss += __shfl_xor_sync(0xffffffffu, ss, o);
    if (lane == 0) rv[row] = rsqrtf(ss * (1.0f/512.0f) + 1e-6f);
}
__global__ void prep_all(const float* __restrict__ wq, const float* __restrict__ wk,
                         const float* __restrict__ wv, const float* __restrict__ wo,
                         const float* __restrict__ wg, const float* __restrict__ wu,
                         const float* __restrict__ wd,
                         const float* __restrict__ inputs,
                         const float* __restrict__ ln1,
                         const float* __restrict__ attn_ln,
                         const float* __restrict__ ln2,
                         const float* __restrict__ mask,
                         float* __restrict__ r1) {
    PDL_TRIGGER();
    int id = blockIdx.x;
    if (id < 1024) {
        int t = id >> 8, r = id & 255;
        const float* src = (t==0)?wq:(t==1)?wk:(t==2)?wv:wo;
        float* dst = (t==0)?g_wq:(t==1)?g_wk:(t==2)?g_wv:g_wo;
        const float* sv = (t==3) ? attn_ln : ln1;
        trans_tile(src, dst, 512, 512, (r & 15)*32, (r >> 4)*32, sv);
    } else if (id < 3072) {
        int t = (id - 1024) >> 10, r = (id - 1024) & 1023;
        trans_tile(t ? wu : wg, t ? g_wu : g_wg, 512, 2048, (r & 63)*32, (r >> 6)*32, ln2);
    } else if (id < 4096) {
        int r = id - 3072;
        trans_tile(wd, g_wd, 2048, 512, (r & 15)*32, (r >> 4)*32, nullptr);
    } else if (id < 4224) {
        rms_r(inputs, r1, (id - 4096)*8 + threadIdx.y);
    } else {
        int tid = threadIdx.y*32 + threadIdx.x;
        #pragma unroll
        for (int j = 0; j < 4; j++) {
            g_ssqA[tid + j*256] = 0.0f;
            g_ssq2[tid + j*256] = 0.0f;
        }
        int lane = threadIdx.x, warp = threadIdx.y;
        #pragma unroll
        for (int p = 0; p < 4; p++) {
            int pair = warp + p*8;
            int b = pair >> 4, c = pair & 15;
            float d = 1.0f - mask[b*S_ + c*CC + lane];
            float pp = d;
            #pragma unroll
            for (int o = 1; o < 32; o <<= 1) {
                float n = __shfl_up_sync(0xffffffffu, pp, o);
                if (lane >= o) pp *= n;
            }
            g_Lg[pair*CC + lane] = pp;
            if (lane == 31) g_chunkP2[pair] = pp;
        }
    }
}

// ============================================================================
// cp.async + ldmatrix tf32 GEMM. 256 thr = 8 warps (4m x 2n). BM=64, BN=64.
// ============================================================================
template<int EPI, int STAGES, int CVT>
__global__ __launch_bounds__(256) void gemm_tc(const float* __restrict__ A,
                                               const float* __restrict__ Wt,
                                               float* __restrict__ C,
                                               int K, int N, int lda, int ldb, int ksplit,
                                               const float* __restrict__ bias,
                                               const float* __restrict__ resid,
                                               const float* __restrict__ ssq_in,
                                               float* __restrict__ ssq_out) {
    PDL_TRIGGER();
    extern __shared__ float smem[];
    float (*As)[64][36] = (float(*)[64][36])smem;
    float (*Bs)[64][36] = (float(*)[64][36])(smem + STAGES*64*36);

    if (ksplit) {
        size_t kz = blockIdx.z;
        A  += kz * ksplit;
        Wt += kz * ksplit;
        C  += kz * (size_t)gridDim.y * 64 * N;
    }
    int m0 = blockIdx.y*64, n0 = blockIdx.x*64;
    int tid = threadIdx.x;
    int warp = tid>>5, lane = tid&31, g = lane>>2, tg = lane&3;
    int mw = (warp>>1)*16, nw = (warp&1)*32;
    int kt = K >> 5;

    int a_r = ((lane>>3)&1)*8 + (lane&7), a_c = (lane>>4)*4;
    int b_r = (lane>>4)*8 + (lane&7),     b_c = ((lane>>3)&1)*4;

    int qa_n[2], qa_c[2];
    #pragma unroll
    for (int r = 0; r < 2; r++) { int q = tid + r*256; qa_n[r] = q>>3; qa_c[r] = (q&7)*4; }

    auto issue = [&](int it2) {
        int s_ = it2 % STAGES; int k0_ = it2 << 5;
        #pragma unroll
        for (int r = 0; r < 2; r++) {
            cpa16(s2u(&As[s_][qa_n[r]][qa_c[r]]), A  + (size_t)(m0+qa_n[r])*lda + k0_ + qa_c[r]);
            cpa16(s2u(&Bs[s_][qa_n[r]][qa_c[r]]), Wt + (size_t)(n0+qa_n[r])*ldb + k0_ + qa_c[r]);
        }
    };

    PDL_WAIT();
    #pragma unroll
    for (int i = 0; i < STAGES-1; i++) { issue(i); CP_COMMIT(); }

    float acc[4][4] = {};
    for (int it = 0; it < kt; it++) {
        asm volatile("cp.async.wait_group %0;" :: "n"(STAGES-2));
        __syncthreads();
        int s = it % STAGES;
        #pragma unroll
        for (int ks = 0; ks < 4; ks++) {
            unsigned a[4], b[4][2];
            ldsm4(a[0], a[1], a[2], a[3], s2u(&As[s][mw + a_r][ks*8 + a_c]));
            if (CVT) {
                #pragma unroll
                for (int j = 0; j < 4; j++) a[j] = f2tf32(__uint_as_float(a[j]));
            }
            #pragma unroll
            for (int p = 0; p < 2; p++)
                ldsm4(b[2*p][0], b[2*p][1], b[2*p+1][0], b[2*p+1][1],
                      s2u(&Bs[s][nw + p*16 + b_r][ks*8 + b_c]));
            #pragma unroll
            for (int nt = 0; nt < 4; nt++)
                mma_tf32(acc[nt], a, b[nt]);
        }
        if (it + STAGES-1 < kt) issue(it + STAGES-1);
        CP_COMMIT();
        __syncthreads();
    }

    if (EPI == 2) {
        int r0 = m0 + mw + g;
        float rs0 = rsqrtf(ssq_in[r0    ] * (1.0f/512.0f) + 1e-6f);
        float rs1 = rsqrtf(ssq_in[r0 + 8] * (1.0f/512.0f) + 1e-6f);
        float ls0 = 0.f, ls1 = 0.f;
        #pragma unroll
        for (int nt = 0; nt < 4; nt++) {
            int c0 = n0 + nw + nt*8 + tg*2;
            #pragma unroll
            for (int h = 0; h < 2; h++) {
                int r = r0 + h*8;
                float rs = h ? rs1 : rs0;
                #pragma unroll
                for (int w2 = 0; w2 < 2; w2++) {
                    int c = c0 + w2;
                    float v = acc[nt][h*2 + w2]*rs + bias[c] + resid[(size_t)r*N + c];
                    C[(size_t)r*N + c] = v;
                    if (h) ls1 += v*v; else ls0 += v*v;
                }
            }
        }
        #pragma unroll
        for (int o = 1; o < 4; o <<= 1) {
            ls0 += __shfl_xor_sync(0xffffffffu, ls0, o);
            ls1 += __shfl_xor_sync(0xffffffffu, ls1, o);
        }
        if (tg == 0) {
            atomicAdd(&ssq_out[r0    ], ls0);
            atomicAdd(&ssq_out[r0 + 8], ls1);
        }
    } else {
        #pragma unroll
        for (int nt = 0; nt < 4; nt++) {
            int c0 = n0 + nw + nt*8 + tg*2;
            #pragma unroll
            for (int h = 0; h < 2; h++) {
                int r = m0 + mw + g + h*8;
                #pragma unroll
                for (int w2 = 0; w2 < 2; w2++)
                    C[(size_t)r*N + c0 + w2] = acc[nt][h*2 + w2];
            }
        }
    }
}

// ---------------- Wd split-K=4 reduce: out = p0+p1+p2+p3 + y1 ----------------
__global__ __launch_bounds__(256) void wd_reduce(float* __restrict__ outx,
                                                 const float* __restrict__ y1) {
    PDL_TRIGGER();
    int i = blockIdx.x*256 + threadIdx.x;
    PDL_WAIT();
    const float4* p = (const float4*)g_wdpart;
    float4 a = p[i], b = p[i + 131072], c = p[i + 262144], d = p[i + 393216];
    float4 r = ((const float4*)y1)[i];
    float4 o;
    o.x = a.x + b.x + c.x + d.x + r.x;
    o.y = a.y + b.y + c.y + d.y + r.y;
    o.z = a.z + b.z + c.z + d.z + r.z;
    o.w = a.w + b.w + c.w + d.w + r.w;
    ((float4*)outx)[i] = o;
}

// ---------------- fused QKV: raw inputs, fragment cvt, epilogue x r1 ----------------
__global__ __launch_bounds__(256) void gemm_qkv_tc(const float* __restrict__ A) {
    PDL_TRIGGER();
    constexpr int STAGES = 3;
    extern __shared__ float smem[];
    float (*As)[128][36] = (float(*)[128][36])smem;
    float (*Bs)[64][36]  = (float(*)[64][36])(smem + STAGES*128*36);

    int n0g = blockIdx.x * 64;
    int sel = n0g >> 9;
    int n0  = n0g & 511;
    const float* Wt = (sel == 0) ? g_wq : (sel == 1) ? g_wk : g_wv;
    float* C = (sel == 0) ? g_q : (sel == 1) ? g_k : g_v;
    bool relu = (sel < 2);
    int m0 = blockIdx.y * 128;
    int tid = threadIdx.x;
    int warp = tid>>5, lane = tid&31, g = lane>>2, tg = lane&3;
    int mw = (warp>>1)*32, nw = (warp&1)*32;
    const int K = 512, N = 512;
    const int kt = 16;

    int a_r = ((lane>>3)&1)*8 + (lane&7), a_c = (lane>>4)*4;
    int b_r = (lane>>4)*8 + (lane&7),     b_c = ((lane>>3)&1)*4;

    int qa_m[4], qa_c[4];
    #pragma unroll
    for (int r = 0; r < 4; r++) { int q = tid + r*256; qa_m[r] = q>>3; qa_c[r] = (q&7)*4; }
    int qb_n[2], qb_c[2];
    #pragma unroll
    for (int r = 0; r < 2; r++) { int q = tid + r*256; qb_n[r] = q>>3; qb_c[r] = (q&7)*4; }

    auto issue = [&](int it2) {
        int s_ = it2 % STAGES; int k0_ = it2 << 5;
        #pragma unroll
        for (int r = 0; r < 4; r++)
            cpa16(s2u(&As[s_][qa_m[r]][qa_c[r]]), A + (size_t)(m0+qa_m[r])*K + k0_ + qa_c[r]);
        #pragma unroll
        for (int r = 0; r < 2; r++)
            cpa16(s2u(&Bs[s_][qb_n[r]][qb_c[r]]), Wt + (size_t)(n0+qb_n[r])*K + k0_ + qb_c[r]);
    };

    PDL_WAIT();
    issue(0); CP_COMMIT();
    issue(1); CP_COMMIT();

    float acc[2][4][4] = {};
    for (int it = 0; it < kt; it++) {
        asm volatile("cp.async.wait_group 1;");
        __syncthreads();
        int s = it % STAGES;
        #pragma unroll
        for (int ks = 0; ks < 4; ks++) {
            unsigned a[2][4], b[4][2];
            #pragma unroll
            for (int mt = 0; mt < 2; mt++) {
                ldsm4(a[mt][0], a[mt][1], a[mt][2], a[mt][3],
                      s2u(&As[s][mw + mt*16 + a_r][ks*8 + a_c]));
                #pragma unroll
                for (int j = 0; j < 4; j++)
                    a[mt][j] = f2tf32(__uint_as_float(a[mt][j]));
            }
            #pragma unroll
            for (int p = 0; p < 2; p++)
                ldsm4(b[2*p][0], b[2*p][1], b[2*p+1][0], b[2*p+1][1],
                      s2u(&Bs[s][nw + p*16 + b_r][ks*8 + b_c]));
            #pragma unroll
            for (int mt = 0; mt < 2; mt++)
                #pragma unroll
                for (int nt = 0; nt < 4; nt++)
                    mma_tf32(acc[mt][nt], a[mt], b[nt]);
        }
        if (it + STAGES-1 < kt) issue(it + STAGES-1);
        CP_COMMIT();
        __syncthreads();
    }

    #pragma unroll
    for (int mt = 0; mt < 2; mt++)
        #pragma unroll
        for (int nt = 0; nt < 4; nt++) {
            int c0 = n0 + nw + nt*8 + tg*2;
            #pragma unroll
            for (int h = 0; h < 2; h++) {
                int r = m0 + mw + mt*16 + g + h*8;
                float rs = g_r1[r];
                #pragma unroll
                for (int w2 = 0; w2 < 2; w2++) {
                    float v = acc[mt][nt][h*2 + w2] * rs;
                    if (relu) v = fmaxf(v, 0.0f);
                    C[(size_t)r*N + c0 + w2] = v;
                }
            }
        }
}

// ---------------- fused Wg/Wu: raw y1, fragment cvt, rs from ssq2, silu(g)*u ----------------
__global__ __launch_bounds__(256) void gemm_gu_tc(const float* __restrict__ A) {
    PDL_TRIGGER();
    constexpr int STAGES = 3;
    extern __shared__ float smem[];
    float (*As)[128][36] = (float(*)[128][36])smem;
    float (*Gs)[64][36]  = (float(*)[64][36])(smem + STAGES*128*36);
    float (*Us)[64][36]  = (float(*)[64][36])(smem + STAGES*128*36 + STAGES*64*36);

    int n0 = blockIdx.x*64, m0 = blockIdx.y*128;
    int tid = threadIdx.x;
    int warp = tid>>5, lane = tid&31, g = lane>>2, tg = lane&3;
    int mw = (warp>>1)*32, nw = (warp&1)*32;
    const int K = 512, N = 2048;
    const int kt = 16;

    int a_r = ((lane>>3)&1)*8 + (lane&7), a_c = (lane>>4)*4;
    int b_r = (lane>>4)*8 + (lane&7),     b_c = ((lane>>3)&1)*4;

    int qa_m[4], qa_c[4];
    #pragma unroll
    for (int r = 0; r < 4; r++) { int q = tid + r*256; qa_m[r] = q>>3; qa_c[r] = (q&7)*4; }
    int qb_n[2], qb_c[2];
    #pragma unroll
    for (int r = 0; r < 2; r++) { int q = tid + r*256; qb_n[r] = q>>3; qb_c[r] = (q&7)*4; }

    auto issue = [&](int it2) {
        int s_ = it2 % STAGES; int k0_ = it2 << 5;
        #pragma unroll
        for (int r = 0; r < 4; r++)
            cpa16(s2u(&As[s_][qa_m[r]][qa_c[r]]), A + (size_t)(m0+qa_m[r])*K + k0_ + qa_c[r]);
        #pragma unroll
        for (int r = 0; r < 2; r++) {
            cpa16(s2u(&Gs[s_][qb_n[r]][qb_c[r]]), g_wg + (size_t)(n0+qb_n[r])*K + k0_ + qb_c[r]);
            cpa16(s2u(&Us[s_][qb_n[r]][qb_c[r]]), g_wu + (size_t)(n0+qb_n[r])*K + k0_ + qb_c[r]);
        }
    };

    PDL_WAIT();
    issue(0); CP_COMMIT();
    issue(1); CP_COMMIT();

    float accg[2][4][4] = {};
    float accu[2][4][4] = {};
    for (int it = 0; it < kt; it++) {
        asm volatile("cp.async.wait_group 1;");
        __syncthreads();
        int s = it % STAGES;
        #pragma unroll
        for (int ks = 0; ks < 4; ks++) {
            unsigned a[2][4], bg[4][2], bu[4][2];
            #pragma unroll
            for (int mt = 0; mt < 2; mt++) {
                ldsm4(a[mt][0], a[mt][1], a[mt][2], a[mt][3],
                      s2u(&As[s][mw + mt*16 + a_r][ks*8 + a_c]));
                #pragma unroll
                for (int j = 0; j < 4; j++)
                    a[mt][j] = f2tf32(__uint_as_float(a[mt][j]));
            }
            #pragma unroll
            for (int p = 0; p < 2; p++) {
                ldsm4(bg[2*p][0], bg[2*p][1], bg[2*p+1][0], bg[2*p+1][1],
                      s2u(&Gs[s][nw + p*16 + b_r][ks*8 + b_c]));
                ldsm4(bu[2*p][0], bu[2*p][1], bu[2*p+1][0], bu[2*p+1][1],
                      s2u(&Us[s][nw + p*16 + b_r][ks*8 + b_c]));
            }
            #pragma unroll
            for (int mt = 0; mt < 2; mt++)
                #pragma unroll
                for (int nt = 0; nt < 4; nt++) {
                    mma_tf32(accg[mt][nt], a[mt], bg[nt]);
                    mma_tf32(accu[mt][nt], a[mt], bu[nt]);
                }
        }
        if (it + STAGES-1 < kt) issue(it + STAGES-1);
        CP_COMMIT();
        __syncthreads();
    }

    float rsr[2][2];
    #pragma unroll
    for (int mt = 0; mt < 2; mt++)
        #pragma unroll
        for (int h = 0; h < 2; h++)
            rsr[mt][h] = rsqrtf(g_ssq2[m0 + mw + mt*16 + g + h*8] * (1.0f/512.0f) + 1e-6f);

    #pragma unroll
    for (int mt = 0; mt < 2; mt++)
        #pragma unroll
        for (int nt = 0; nt < 4; nt++) {
            int c0 = n0 + nw + nt*8 + tg*2;
            #pragma unroll
            for (int h = 0; h < 2; h++) {
                int r = m0 + mw + mt*16 + g + h*8;
                float rs = rsr[mt][h];
                #pragma unroll
                for (int w2 = 0; w2 < 2; w2++) {
                    float gg = accg[mt][nt][h*2 + w2] * rs;
                    float uu = accu[mt][nt][h*2 + w2] * rs;
                    float hv = (gg / (1.0f + expf(-gg))) * uu;
                    g_hbuf[(size_t)r*N + c0 + w2] = rnd32(hv);
                }
            }
        }
}

// ---------------- attention pass A ----------------
__global__ __launch_bounds__(256) void attn_passA() {
    PDL_TRIGGER();
    int c  = blockIdx.x % NC;
    int bh = blockIdx.x / NC;
    int b = bh / H_, h = bh % H_;
    __shared__ float Ks[CC][HD_+4];
    __shared__ float Vs[CC][HD_+4];
    __shared__ float Ws[CC];
    int tid = threadIdx.x;
    PDL_WAIT();
    #pragma unroll
    for (int r = 0; r < 2; r++) {
        int idx = tid + r*256;
        int t = idx >> 4, d4 = (idx & 15) * 4;
        size_t gbase = (size_t)(b*S_ + c*CC + t)*HID_ + h*HD_ + d4;
        *(float4*)&Ks[t][d4] = *(const float4*)(g_k + gbase);
        *(float4*)&Vs[t][d4] = *(const float4*)(g_v + gbase);
    }
    if (tid < 32) {
        float lg = g_Lg[(b*NC + c)*CC + tid];
        float P  = g_chunkP2[b*NC + c];
        Ws[tid] = P / lg;
    }
    __syncthreads();
    int tx = tid & 15, ty = tid >> 4;
    float acc[4][4] = {};
    #pragma unroll 8
    for (int i = 0; i < CC; i++) {
        float w = Ws[i];
        float4 av = *(const float4*)&Vs[i][ty*4];
        float4 bv = *(const float4*)&Ks[i][tx*4];
        float a[4] = {w*av.x, w*av.y, w*av.z, w*av.w};
        float bb[4] = {bv.x, bv.y, bv.z, bv.w};
        #pragma unroll
        for (int x = 0; x < 4; x++)
            #pragma unroll
            for (int y = 0; y < 4; y++)
                acc[x][y] = fmaf(a[x], bb[y], acc[x][y]);
    }
    float* Sp = g_Schunk + (size_t)(bh*NC + c)*HD_*HD_;
    #pragma unroll
    for (int x = 0; x < 4; x++) {
        float4 o4 = {acc[x][0], acc[x][1], acc[x][2], acc[x][3]};
        *(float4*)(Sp + (ty*4 + x)*HD_ + tx*4) = o4;
    }
}

// ---------------- attention pass B: parallel scan ----------------
__global__ __launch_bounds__(256) void attn_passB(const float* __restrict__ carry,
                                                  float* __restrict__ carry_out) {
    PDL_TRIGGER();
    int e  = blockIdx.x * 256 + threadIdx.x;
    int bh = e >> 12;
    int idx = e & 4095;
    const float* Sc = g_Schunk + (size_t)bh*NC*4096 + idx;
    float*       So = g_Sstart + (size_t)bh*NC*4096 + idx;
    int b = bh >> 3;
    PDL_WAIT();
    float sc[NC], pp[NC];
    #pragma unroll
    for (int c = 0; c < NC; c++) sc[c] = Sc[c*4096];
    #pragma unroll
    for (int c = 0; c < NC; c++) pp[c] = __ldg(&g_chunkP2[b*NC + c]);
    float st = carry[e];
    #pragma unroll
    for (int c = 0; c < NC; c++) {
        So[c*4096] = st;
        st = st * pp[c] + sc[c];
    }
    carry_out[e] = st;
}

// ---------------- attention pass C (+ fused ssqA atomics) ----------------
__global__ __launch_bounds__(256) void attn_passC() {
    PDL_TRIGGER();
    int c  = blockIdx.x % NC;
    int bh = blockIdx.x / NC;
    int b = bh / H_, h = bh % H_;
    __shared__ float Qs [CC][HD_+4];
    __shared__ float KVs[CC][HD_+4];
    __shared__ float SsT[HD_][HD_+4];
    __shared__ float Gs [CC][CC+1];
    __shared__ float Lg [CC];
    int tid = threadIdx.x;
    PDL_WAIT();
    #pragma unroll
    for (int r = 0; r < 2; r++) {
        int idx = tid + r*256;
        int t = idx >> 4, d4 = (idx & 15) * 4;
        size_t gbase = (size_t)(b*S_ + c*CC + t)*HID_ + h*HD_ + d4;
        *(float4*)&Qs[t][d4]  = *(const float4*)(g_q + gbase);
        *(float4*)&KVs[t][d4] = *(const float4*)(g_k + gbase);
    }
    const float* Sp = g_Sstart + (size_t)(bh*NC + c)*4096;
    #pragma unroll
    for (int r = 0; r < 4; r++) {
        int idx = tid + r*256;
        int row = idx >> 4, c4 = (idx & 15) * 4;
        float4 sv = *(const float4*)(Sp + row*HD_ + c4);
        SsT[c4+0][row] = sv.x; SsT[c4+1][row] = sv.y;
        SsT[c4+2][row] = sv.z; SsT[c4+3][row] = sv.w;
    }
    if (tid < 32) Lg[tid] = g_Lg[(b*NC + c)*CC + tid];
    __syncthreads();
    #pragma unroll
    for (int r = 0; r < 4; r++) {
        int e = tid + r*256;
        int t = e >> 5, i = e & 31;
        float gacc = 0.0f;
        if (i <= t) {
            #pragma unroll
            for (int d4 = 0; d4 < HD_; d4 += 4) {
                float4 qv = *(const float4*)&Qs[t][d4];
                float4 kv = *(const float4*)&KVs[i][d4];
                gacc += qv.x*kv.x + qv.y*kv.y + qv.z*kv.z + qv.w*kv.w;
            }
            gacc *= Lg[t] / Lg[i];
        }
        Gs[t][i] = gacc;
    }
    __syncthreads();
    #pragma unroll
    for (int r = 0; r < 2; r++) {
        int idx = tid + r*256;
        int t = idx >> 4, d4 = (idx & 15) * 4;
        *(float4*)&KVs[t][d4] =
            *(const float4*)(g_v + (size_t)(b*S_ + c*CC + t)*HID_ + h*HD_ + d4);
    }
    __syncthreads();
    int t  = tid >> 3;
    int a0 = (tid & 7) * 8;
    float acc[8] = {};
    #pragma unroll 8
    for (int bb = 0; bb < HD_; bb++) {
        float qv = Qs[t][bb];
        float4 s0 = *(const float4*)&SsT[bb][a0];
        float4 s1 = *(const float4*)&SsT[bb][a0+4];
        acc[0] = fmaf(s0.x, qv, acc[0]); acc[1] = fmaf(s0.y, qv, acc[1]);
        acc[2] = fmaf(s0.z, qv, acc[2]); acc[3] = fmaf(s0.w, qv, acc[3]);
        acc[4] = fmaf(s1.x, qv, acc[4]); acc[5] = fmaf(s1.y, qv, acc[5]);
        acc[6] = fmaf(s1.z, qv, acc[6]); acc[7] = fmaf(s1.w, qv, acc[7]);
    }
    float lt = Lg[t];
    #pragma unroll
    for (int j = 0; j < 8; j++) acc[j] *= lt;
    #pragma unroll 8
    for (int i = 0; i < CC; i++) {
        float gg = Gs[t][i];
        float4 v0 = *(const float4*)&KVs[i][a0];
        float4 v1 = *(const float4*)&KVs[i][a0+4];
        acc[0] = fmaf(gg, v0.x, acc[0]); acc[1] = fmaf(gg, v0.y, acc[1]);
        acc[2] = fmaf(gg, v0.z, acc[2]); acc[3] = fmaf(gg, v0.w, acc[3]);
        acc[4] = fmaf(gg, v1.x, acc[4]); acc[5] = fmaf(gg, v1.y, acc[5]);
        acc[6] = fmaf(gg, v1.z, acc[6]); acc[7] = fmaf(gg, v1.w, acc[7]);
    }
    float* op = g_attn + (size_t)(b*S_ + c*CC + t)*HID_ + h*HD_ + a0;
    float4 o0 = {acc[0], acc[1], acc[2], acc[3]};
    float4 o1 = {acc[4], acc[5], acc[6], acc[7]};
    *(float4*)op = o0;
    *(float4*)(op + 4) = o1;
    float ls = acc[0]*acc[0] + acc[1]*acc[1] + acc[2]*acc[2] + acc[3]*acc[3]
             + acc[4]*acc[4] + acc[5]*acc[5] + acc[6]*acc[6] + acc[7]*acc[7];
    #pragma unroll
    for (int o = 1; o < 8; o <<= 1) ls += __shfl_xor_sync(0xffffffffu, ls, o);
    if ((tid & 7) == 0) atomicAdd(&g_ssqA[b*S_ + c*CC + t], ls);
}

// ---------------- host launcher ----------------
static cudaLaunchConfig_t make_cfg(dim3 grid, dim3 block, size_t smem,
                                   cudaLaunchAttribute* attr) {
    cudaLaunchConfig_t cfg = {};
    cfg.gridDim = grid;
    cfg.blockDim = block;
    cfg.dynamicSmemBytes = smem;
    cfg.stream = 0;
    attr->id = cudaLaunchAttributeProgrammaticStreamSerialization;
    attr->val.programmaticStreamSerializationAllowed = 1;
    cfg.attrs = attr;
    cfg.numAttrs = 1;
    return cfg;
}

extern "C" void kernel_launch(void* const* d_in, const int* in_sizes, int n_in,
                              void* d_out, int out_size) {
    const float* inputs  = (const float*)d_in[0];
    const float* mask    = (const float*)d_in[1];
    const float* carry   = (const float*)d_in[2];
    const float* ln1     = (const float*)d_in[3];
    const float* Wq      = (const float*)d_in[4];
    const float* Wk      = (const float*)d_in[5];
    const float* Wv      = (const float*)d_in[6];
    const float* attn_ln = (const float*)d_in[7];
    const float* Wo      = (const float*)d_in[8];
    const float* bo      = (const float*)d_in[9];
    const float* ln2     = (const float*)d_in[10];
    const float* Wg      = (const float*)d_in[11];
    const float* Wu      = (const float*)d_in[12];
    const float* Wd      = (const float*)d_in[13];

    float* out        = (float*)d_out;
    float* out_carry  = out;
    float* out_x      = out + B_*H_*HD_*HD_;

    float *p_attn, *p_y1, *p_hbuf, *p_wo, *p_wd, *p_wdpart, *p_r1, *p_ssqA, *p_ssq2;
    cudaGetSymbolAddress((void**)&p_attn,  g_attn);
    cudaGetSymbolAddress((void**)&p_y1,    g_y1);
    cudaGetSymbolAddress((void**)&p_hbuf,  g_hbuf);
    cudaGetSymbolAddress((void**)&p_wo,    g_wo);
    cudaGetSymbolAddress((void**)&p_wd,    g_wd);
    cudaGetSymbolAddress((void**)&p_wdpart, g_wdpart);
    cudaGetSymbolAddress((void**)&p_r1,    g_r1);
    cudaGetSymbolAddress((void**)&p_ssqA,  g_ssqA);
    cudaGetSymbolAddress((void**)&p_ssq2,  g_ssq2);

    const int smem_s   = 4*(64*36 + 64*36)*4;            // 73728
    const int smem_qkv = 3*(128*36 + 64*36)*4;           // 82944
    const int smem_gu  = 3*(128*36 + 2*64*36)*4;         // 110592

    cudaFuncSetAttribute((const void*)gemm_tc<0,4,0>, cudaFuncAttributeMaxDynamicSharedMemorySize, smem_s);
    cudaFuncSetAttribute((const void*)gemm_tc<2,4,1>, cudaFuncAttributeMaxDynamicSharedMemorySize, smem_s);
    cudaFuncSetAttribute((const void*)gemm_qkv_tc,    cudaFuncAttributeMaxDynamicSharedMemorySize, smem_qkv);
    cudaFuncSetAttribute((const void*)gemm_gu_tc,     cudaFuncAttributeMaxDynamicSharedMemorySize, smem_gu);

    cudaLaunchAttribute at[8];

    // 1. prep (no PDL attr; first in chain)
    prep_all<<<4225, dim3(32, 8)>>>(Wq, Wk, Wv, Wo, Wg, Wu, Wd,
                                    inputs, ln1, attn_ln, ln2, mask, p_r1);
    // 2. q,k,v
    {
        cudaLaunchConfig_t c = make_cfg(dim3(24, 8), dim3(256), smem_qkv, &at[0]);
        cudaLaunchKernelEx(&c, gemm_qkv_tc, inputs);
    }
    // 3-5. chunked linear attention
    {
        cudaLaunchConfig_t c = make_cfg(dim3(B_*H_*NC), dim3(256), 0, &at[1]);
        cudaLaunchKernelEx(&c, attn_passA);
    }
    {
        cudaLaunchConfig_t c = make_cfg(dim3(256), dim3(256), 0, &at[2]);
        cudaLaunchKernelEx(&c, attn_passB, carry, out_carry);
    }
    {
        cudaLaunchConfig_t c = make_cfg(dim3(B_*H_*NC), dim3(256), 0, &at[3]);
        cudaLaunchKernelEx(&c, attn_passC);
    }
    // 6. y1 = rsA*(attn @ wo') + bo + inputs; accumulates ssq2
    {
        cudaLaunchConfig_t c = make_cfg(dim3(8, 16), dim3(256), smem_s, &at[4]);
        cudaLaunchKernelEx(&c, gemm_tc<2, 4, 1>, (const float*)p_attn, (const float*)p_wo,
                           (float*)p_y1, 512, 512, 512, 512, 0,
                           bo, inputs, (const float*)p_ssqA, (float*)p_ssq2);
    }
    // 7. h = silu(rs2*(y1@wg')) * (rs2*(y1@wu'))
    {
        cudaLaunchConfig_t c = make_cfg(dim3(32, 8), dim3(256), smem_gu, &at[5]);
        cudaLaunchKernelEx(&c, gemm_gu_tc, (const float*)p_y1);
    }
    // 8. Wd partials: split-K=4
    {
        cudaLaunchConfig_t c = make_cfg(dim3(8, 16, 4), dim3(256), smem_s, &at[6]);
        cudaLaunchKernelEx(&c, gemm_tc<0, 4, 0>, (const float*)p_hbuf, (const float*)p_wd,
                           (float*)p_wdpart, 512, 512, 2048, 2048, 512,
                           (const float*)nullptr, (const float*)nullptr,
                           (const float*)nullptr, (float*)nullptr);
    }
    // 9. out_x = sum(partials) + y1
    {
        cudaLaunchConfig_t c = make_cfg(dim3(512), dim3(256), 0, &at[7]);
        cudaLaunchKernelEx(&c, wd_reduce, out_x, (const float*)p_y1);
    }
}

// round 16
// speedup vs baseline: 1.2390x; 1.2390x over previous
#include <cuda_runtime.h>
#include <math.h>
#include <stdint.h>

#define B_   2
#define S_   512
#define D_   512
#define H_   8
#define HD_  64
#define HID_ 512
#define FFN_ 2048
#define CC   32
#define NC   (S_/CC)
#define ROWS (B_*S_)

// ---------------- scratch (device globals) ----------------
__device__ float g_q    [ROWS*HID_];
__device__ float g_k    [ROWS*HID_];
__device__ float g_v    [ROWS*HID_];
__device__ float g_attn [ROWS*HID_];
__device__ float g_y1   [ROWS*D_];
__device__ float g_hbuf [ROWS*FFN_];
__device__ float g_Schunk[B_*H_*NC*HD_*HD_];
__device__ float g_Sstart[B_*H_*NC*HD_*HD_];
__device__ float g_Lg     [B_*NC*CC];
__device__ float g_chunkP2[B_*NC];
__device__ float g_r1   [ROWS];
__device__ float g_ssqA [ROWS];
__device__ float g_ssq2 [ROWS];
// tf32-rounded, TRANSPOSED weights with ln folded: Wt[n][k]
__device__ float g_wq[HID_*D_];
__device__ float g_wk[HID_*D_];
__device__ float g_wv[HID_*D_];
__device__ float g_wo[D_*HID_];
__device__ float g_wg[FFN_*D_];
__device__ float g_wu[FFN_*D_];
__device__ float g_wd[D_*FFN_];

// ---------------- helpers ----------------
__device__ __forceinline__ unsigned f2tf32(float x) {
    unsigned r; asm("cvt.rna.tf32.f32 %0, %1;" : "=r"(r) : "f"(x)); return r;
}
__device__ __forceinline__ float rnd32(float x) { return __uint_as_float(f2tf32(x)); }
__device__ __forceinline__ void mma_tf32(float* d, const unsigned* a, const unsigned* b) {
    asm("mma.sync.aligned.m16n8k8.row.col.f32.tf32.tf32.f32 "
        "{%0,%1,%2,%3}, {%4,%5,%6,%7}, {%8,%9}, {%0,%1,%2,%3};"
        : "+f"(d[0]), "+f"(d[1]), "+f"(d[2]), "+f"(d[3])
        : "r"(a[0]), "r"(a[1]), "r"(a[2]), "r"(a[3]), "r"(b[0]), "r"(b[1]));
}
__device__ __forceinline__ uint32_t s2u(const void* p) {
    return (uint32_t)__cvta_generic_to_shared(p);
}
__device__ __forceinline__ void cpa16(uint32_t d, const void* g) {
    asm volatile("cp.async.cg.shared.global [%0], [%1], 16;" :: "r"(d), "l"(g));
}
#define CP_COMMIT() asm volatile("cp.async.commit_group;")
__device__ __forceinline__ void ldsm4(unsigned& r0, unsigned& r1, unsigned& r2, unsigned& r3,
                                      uint32_t addr) {
    asm volatile("ldmatrix.sync.aligned.m8n8.x4.shared.b16 {%0,%1,%2,%3}, [%4];"
                 : "=r"(r0), "=r"(r1), "=r"(r2), "=r"(r3) : "r"(addr));
}

// ============================================================
// prep kernel.  block = (32, 8).  Block map:
//   [0,1024)    : wq/wk/wv (x ln1) + wo (x attn_ln)   512x512
//   [1024,3072) : wg/wu (x ln2)                        K=512 N=2048
//   [3072,4096) : wd (no scale)                        K=2048 N=512
//   [4096,4224) : r1 per row
//   4224        : mask decay scan + zero ssq buffers
// ============================================================
__device__ __forceinline__ void trans_tile(const float* __restrict__ W,
                                           float* __restrict__ Wt,
                                           int K, int N, int n0, int k0,
                                           const float* __restrict__ svec) {
    __shared__ float t[32][33];
    int x = threadIdx.x, y = threadIdx.y;
    #pragma unroll
    for (int i = 0; i < 32; i += 8)
        t[y+i][x] = W[(size_t)(k0+y+i)*N + n0 + x];
    __syncthreads();
    float s = svec ? svec[k0 + x] : 1.0f;
    #pragma unroll
    for (int i = 0; i < 32; i += 8)
        Wt[(size_t)(n0+y+i)*K + k0 + x] = rnd32(t[x][y+i] * s);
}
__device__ __forceinline__ void rms_r(const float* __restrict__ x,
                                      float* __restrict__ rv, int row) {
    int lane = threadIdx.x;
    const float4* xp = (const float4*)(x + (size_t)row*512);
    float ss = 0.f;
    #pragma unroll
    for (int i = 0; i < 4; i++) {
        float4 v = xp[lane + 32*i];
        ss += v.x*v.x + v.y*v.y + v.z*v.z + v.w*v.w;
    }
    #pragma unroll
    for (int o = 16; o > 0; o >>= 1) ss += __shfl_xor_sync(0xffffffffu, ss, o);
    if (lane == 0) rv[row] = rsqrtf(ss * (1.0f/512.0f) + 1e-6f);
}
__global__ void prep_all(const float* __restrict__ wq, const float* __restrict__ wk,
                         const float* __restrict__ wv, const float* __restrict__ wo,
                         const float* __restrict__ wg, const float* __restrict__ wu,
                         const float* __restrict__ wd,
                         const float* __restrict__ inputs,
                         const float* __restrict__ ln1,
                         const float* __restrict__ attn_ln,
                         const float* __restrict__ ln2,
                         const float* __restrict__ mask,
                         float* __restrict__ r1) {
    int id = blockIdx.x;
    if (id < 1024) {
        int t = id >> 8, r = id & 255;
        const float* src = (t==0)?wq:(t==1)?wk:(t==2)?wv:wo;
        float* dst = (t==0)?g_wq:(t==1)?g_wk:(t==2)?g_wv:g_wo;
        const float* sv = (t==3) ? attn_ln : ln1;
        trans_tile(src, dst, 512, 512, (r & 15)*32, (r >> 4)*32, sv);
    } else if (id < 3072) {
        int t = (id - 1024) >> 10, r = (id - 1024) & 1023;
        trans_tile(t ? wu : wg, t ? g_wu : g_wg, 512, 2048, (r & 63)*32, (r >> 6)*32, ln2);
    } else if (id < 4096) {
        int r = id - 3072;
        trans_tile(wd, g_wd, 2048, 512, (r & 15)*32, (r >> 4)*32, nullptr);
    } else if (id < 4224) {
        rms_r(inputs, r1, (id - 4096)*8 + threadIdx.y);
    } else {
        int tid = threadIdx.y*32 + threadIdx.x;
        #pragma unroll
        for (int j = 0; j < 4; j++) {
            g_ssqA[tid + j*256] = 0.0f;
            g_ssq2[tid + j*256] = 0.0f;
        }
        int lane = threadIdx.x, warp = threadIdx.y;
        #pragma unroll
        for (int p = 0; p < 4; p++) {
            int pair = warp + p*8;
            int b = pair >> 4, c = pair & 15;
            float d = 1.0f - mask[b*S_ + c*CC + lane];
            float pp = d;
            #pragma unroll
            for (int o = 1; o < 32; o <<= 1) {
                float n = __shfl_up_sync(0xffffffffu, pp, o);
                if (lane >= o) pp *= n;
            }
            g_Lg[pair*CC + lane] = pp;
            if (lane == 31) g_chunkP2[pair] = pp;
        }
    }
}

// ============================================================================
// cp.async + ldmatrix tf32 GEMM. 256 thr = 8 warps (4m x 2n). BM=64, BN=64.
// CVT: rna-round A fragments. EPI:
//   2: rs from ssq_in, C = v*rs + bias + resid, ssq_out += v^2, copy_out = C val
//   4: atomicAdd partial into C (split-K accumulate onto residual-pre-filled C)
// ============================================================================
template<int EPI, int STAGES, int CVT>
__global__ __launch_bounds__(256) void gemm_tc(const float* __restrict__ A,
                                               const float* __restrict__ Wt,
                                               float* __restrict__ C,
                                               int K, int N, int lda, int ldb, int ksplit,
                                               const float* __restrict__ bias,
                                               const float* __restrict__ resid,
                                               const float* __restrict__ ssq_in,
                                               float* __restrict__ ssq_out,
                                               float* __restrict__ copy_out) {
    extern __shared__ float smem[];
    float (*As)[64][36] = (float(*)[64][36])smem;
    float (*Bs)[64][36] = (float(*)[64][36])(smem + STAGES*64*36);

    if (ksplit) {
        size_t kz = blockIdx.z;
        A  += kz * ksplit;
        Wt += kz * ksplit;
    }
    int m0 = blockIdx.y*64, n0 = blockIdx.x*64;
    int tid = threadIdx.x;
    int warp = tid>>5, lane = tid&31, g = lane>>2, tg = lane&3;
    int mw = (warp>>1)*16, nw = (warp&1)*32;
    int kt = K >> 5;

    int a_r = ((lane>>3)&1)*8 + (lane&7), a_c = (lane>>4)*4;
    int b_r = (lane>>4)*8 + (lane&7),     b_c = ((lane>>3)&1)*4;

    int qa_n[2], qa_c[2];
    #pragma unroll
    for (int r = 0; r < 2; r++) { int q = tid + r*256; qa_n[r] = q>>3; qa_c[r] = (q&7)*4; }

    auto issue = [&](int it2) {
        int s_ = it2 % STAGES; int k0_ = it2 << 5;
        #pragma unroll
        for (int r = 0; r < 2; r++) {
            cpa16(s2u(&As[s_][qa_n[r]][qa_c[r]]), A  + (size_t)(m0+qa_n[r])*lda + k0_ + qa_c[r]);
            cpa16(s2u(&Bs[s_][qa_n[r]][qa_c[r]]), Wt + (size_t)(n0+qa_n[r])*ldb + k0_ + qa_c[r]);
        }
    };

    #pragma unroll
    for (int i = 0; i < STAGES-1; i++) { issue(i); CP_COMMIT(); }

    float acc[4][4] = {};
    for (int it = 0; it < kt; it++) {
        asm volatile("cp.async.wait_group %0;" :: "n"(STAGES-2));
        __syncthreads();
        int s = it % STAGES;
        #pragma unroll
        for (int ks = 0; ks < 4; ks++) {
            unsigned a[4], b[4][2];
            ldsm4(a[0], a[1], a[2], a[3], s2u(&As[s][mw + a_r][ks*8 + a_c]));
            if (CVT) {
                #pragma unroll
                for (int j = 0; j < 4; j++) a[j] = f2tf32(__uint_as_float(a[j]));
            }
            #pragma unroll
            for (int p = 0; p < 2; p++)
                ldsm4(b[2*p][0], b[2*p][1], b[2*p+1][0], b[2*p+1][1],
                      s2u(&Bs[s][nw + p*16 + b_r][ks*8 + b_c]));
            #pragma unroll
            for (int nt = 0; nt < 4; nt++)
                mma_tf32(acc[nt], a, b[nt]);
        }
        if (it + STAGES-1 < kt) issue(it + STAGES-1);
        CP_COMMIT();
        __syncthreads();
    }

    if (EPI == 2) {
        int r0 = m0 + mw + g;
        float rs0 = rsqrtf(ssq_in[r0    ] * (1.0f/512.0f) + 1e-6f);
        float rs1 = rsqrtf(ssq_in[r0 + 8] * (1.0f/512.0f) + 1e-6f);
        float ls0 = 0.f, ls1 = 0.f;
        #pragma unroll
        for (int nt = 0; nt < 4; nt++) {
            int c0 = n0 + nw + nt*8 + tg*2;
            #pragma unroll
            for (int h = 0; h < 2; h++) {
                int r = r0 + h*8;
                float rs = h ? rs1 : rs0;
                #pragma unroll
                for (int w2 = 0; w2 < 2; w2++) {
                    int c = c0 + w2;
                    float v = acc[nt][h*2 + w2]*rs + bias[c] + resid[(size_t)r*N + c];
                    C[(size_t)r*N + c] = v;
                    copy_out[(size_t)r*N + c] = v;
                    if (h) ls1 += v*v; else ls0 += v*v;
                }
            }
        }
        #pragma unroll
        for (int o = 1; o < 4; o <<= 1) {
            ls0 += __shfl_xor_sync(0xffffffffu, ls0, o);
            ls1 += __shfl_xor_sync(0xffffffffu, ls1, o);
        }
        if (tg == 0) {
            atomicAdd(&ssq_out[r0    ], ls0);
            atomicAdd(&ssq_out[r0 + 8], ls1);
        }
    } else if (EPI == 4) {
        #pragma unroll
        for (int nt = 0; nt < 4; nt++) {
            int c0 = n0 + nw + nt*8 + tg*2;
            #pragma unroll
            for (int h = 0; h < 2; h++) {
                int r = m0 + mw + g + h*8;
                #pragma unroll
                for (int w2 = 0; w2 < 2; w2++)
                    atomicAdd(&C[(size_t)r*N + c0 + w2], acc[nt][h*2 + w2]);
            }
        }
    } else {
        #pragma unroll
        for (int nt = 0; nt < 4; nt++) {
            int c0 = n0 + nw + nt*8 + tg*2;
            #pragma unroll
            for (int h = 0; h < 2; h++) {
                int r = m0 + mw + g + h*8;
                #pragma unroll
                for (int w2 = 0; w2 < 2; w2++)
                    C[(size_t)r*N + c0 + w2] = acc[nt][h*2 + w2];
            }
        }
    }
}

// ---------------- fused QKV: raw inputs, fragment cvt, epilogue x r1 ----------------
__global__ __launch_bounds__(256) void gemm_qkv_tc(const float* __restrict__ A) {
    constexpr int STAGES = 3;
    extern __shared__ float smem[];
    float (*As)[128][36] = (float(*)[128][36])smem;
    float (*Bs)[64][36]  = (float(*)[64][36])(smem + STAGES*128*36);

    int n0g = blockIdx.x * 64;
    int sel = n0g >> 9;
    int n0  = n0g & 511;
    const float* Wt = (sel == 0) ? g_wq : (sel == 1) ? g_wk : g_wv;
    float* C = (sel == 0) ? g_q : (sel == 1) ? g_k : g_v;
    bool relu = (sel < 2);
    int m0 = blockIdx.y * 128;
    int tid = threadIdx.x;
    int warp = tid>>5, lane = tid&31, g = lane>>2, tg = lane&3;
    int mw = (warp>>1)*32, nw = (warp&1)*32;
    const int K = 512, N = 512;
    const int kt = 16;

    int a_r = ((lane>>3)&1)*8 + (lane&7), a_c = (lane>>4)*4;
    int b_r = (lane>>4)*8 + (lane&7),     b_c = ((lane>>3)&1)*4;

    int qa_m[4], qa_c[4];
    #pragma unroll
    for (int r = 0; r < 4; r++) { int q = tid + r*256; qa_m[r] = q>>3; qa_c[r] = (q&7)*4; }
    int qb_n[2], qb_c[2];
    #pragma unroll
    for (int r = 0; r < 2; r++) { int q = tid + r*256; qb_n[r] = q>>3; qb_c[r] = (q&7)*4; }

    auto issue = [&](int it2) {
        int s_ = it2 % STAGES; int k0_ = it2 << 5;
        #pragma unroll
        for (int r = 0; r < 4; r++)
            cpa16(s2u(&As[s_][qa_m[r]][qa_c[r]]), A + (size_t)(m0+qa_m[r])*K + k0_ + qa_c[r]);
        #pragma unroll
        for (int r = 0; r < 2; r++)
            cpa16(s2u(&Bs[s_][qb_n[r]][qb_c[r]]), Wt + (size_t)(n0+qb_n[r])*K + k0_ + qb_c[r]);
    };

    issue(0); CP_COMMIT();
    issue(1); CP_COMMIT();

    float acc[2][4][4] = {};
    for (int it = 0; it < kt; it++) {
        asm volatile("cp.async.wait_group 1;");
        __syncthreads();
        int s = it % STAGES;
        #pragma unroll
        for (int ks = 0; ks < 4; ks++) {
            unsigned a[2][4], b[4][2];
            #pragma unroll
            for (int mt = 0; mt < 2; mt++) {
                ldsm4(a[mt][0], a[mt][1], a[mt][2], a[mt][3],
                      s2u(&As[s][mw + mt*16 + a_r][ks*8 + a_c]));
                #pragma unroll
                for (int j = 0; j < 4; j++)
                    a[mt][j] = f2tf32(__uint_as_float(a[mt][j]));
            }
            #pragma unroll
            for (int p = 0; p < 2; p++)
                ldsm4(b[2*p][0], b[2*p][1], b[2*p+1][0], b[2*p+1][1],
                      s2u(&Bs[s][nw + p*16 + b_r][ks*8 + b_c]));
            #pragma unroll
            for (int mt = 0; mt < 2; mt++)
                #pragma unroll
                for (int nt = 0; nt < 4; nt++)
                    mma_tf32(acc[mt][nt], a[mt], b[nt]);
        }
        if (it + STAGES-1 < kt) issue(it + STAGES-1);
        CP_COMMIT();
        __syncthreads();
    }

    #pragma unroll
    for (int mt = 0; mt < 2; mt++)
        #pragma unroll
        for (int nt = 0; nt < 4; nt++) {
            int c0 = n0 + nw + nt*8 + tg*2;
            #pragma unroll
            for (int h = 0; h < 2; h++) {
                int r = m0 + mw + mt*16 + g + h*8;
                float rs = g_r1[r];
                #pragma unroll
                for (int w2 = 0; w2 < 2; w2++) {
                    float v = acc[mt][nt][h*2 + w2] * rs;
                    if (relu) v = fmaxf(v, 0.0f);
                    C[(size_t)r*N + c0 + w2] = v;
                }
            }
        }
}

// ---------------- fused Wg/Wu: raw y1, fragment cvt, rs from ssq2, silu(g)*u ----------------
__global__ __launch_bounds__(256) void gemm_gu_tc(const float* __restrict__ A) {
    constexpr int STAGES = 3;
    extern __shared__ float smem[];
    float (*As)[128][36] = (float(*)[128][36])smem;
    float (*Gs)[64][36]  = (float(*)[64][36])(smem + STAGES*128*36);
    float (*Us)[64][36]  = (float(*)[64][36])(smem + STAGES*128*36 + STAGES*64*36);

    int n0 = blockIdx.x*64, m0 = blockIdx.y*128;
    int tid = threadIdx.x;
    int warp = tid>>5, lane = tid&31, g = lane>>2, tg = lane&3;
    int mw = (warp>>1)*32, nw = (warp&1)*32;
    const int K = 512, N = 2048;
    const int kt = 16;

    int a_r = ((lane>>3)&1)*8 + (lane&7), a_c = (lane>>4)*4;
    int b_r = (lane>>4)*8 + (lane&7),     b_c = ((lane>>3)&1)*4;

    int qa_m[4], qa_c[4];
    #pragma unroll
    for (int r = 0; r < 4; r++) { int q = tid + r*256; qa_m[r] = q>>3; qa_c[r] = (q&7)*4; }
    int qb_n[2], qb_c[2];
    #pragma unroll
    for (int r = 0; r < 2; r++) { int q = tid + r*256; qb_n[r] = q>>3; qb_c[r] = (q&7)*4; }

    auto issue = [&](int it2) {
        int s_ = it2 % STAGES; int k0_ = it2 << 5;
        #pragma unroll
        for (int r = 0; r < 4; r++)
            cpa16(s2u(&As[s_][qa_m[r]][qa_c[r]]), A + (size_t)(m0+qa_m[r])*K + k0_ + qa_c[r]);
        #pragma unroll
        for (int r = 0; r < 2; r++) {
            cpa16(s2u(&Gs[s_][qb_n[r]][qb_c[r]]), g_wg + (size_t)(n0+qb_n[r])*K + k0_ + qb_c[r]);
            cpa16(s2u(&Us[s_][qb_n[r]][qb_c[r]]), g_wu + (size_t)(n0+qb_n[r])*K + k0_ + qb_c[r]);
        }
    };

    issue(0); CP_COMMIT();
    issue(1); CP_COMMIT();

    float accg[2][4][4] = {};
    float accu[2][4][4] = {};
    for (int it = 0; it < kt; it++) {
        asm volatile("cp.async.wait_group 1;");
        __syncthreads();
        int s = it % STAGES;
        #pragma unroll
        for (int ks = 0; ks < 4; ks++) {
            unsigned a[2][4], bg[4][2], bu[4][2];
            #pragma unroll
            for (int mt = 0; mt < 2; mt++) {
                ldsm4(a[mt][0], a[mt][1], a[mt][2], a[mt][3],
                      s2u(&As[s][mw + mt*16 + a_r][ks*8 + a_c]));
                #pragma unroll
                for (int j = 0; j < 4; j++)
                    a[mt][j] = f2tf32(__uint_as_float(a[mt][j]));
            }
            #pragma unroll
            for (int p = 0; p < 2; p++) {
                ldsm4(bg[2*p][0], bg[2*p][1], bg[2*p+1][0], bg[2*p+1][1],
                      s2u(&Gs[s][nw + p*16 + b_r][ks*8 + b_c]));
                ldsm4(bu[2*p][0], bu[2*p][1], bu[2*p+1][0], bu[2*p+1][1],
                      s2u(&Us[s][nw + p*16 + b_r][ks*8 + b_c]));
            }
            #pragma unroll
            for (int mt = 0; mt < 2; mt++)
                #pragma unroll
                for (int nt = 0; nt < 4; nt++) {
                    mma_tf32(accg[mt][nt], a[mt], bg[nt]);
                    mma_tf32(accu[mt][nt], a[mt], bu[nt]);
                }
        }
        if (it + STAGES-1 < kt) issue(it + STAGES-1);
        CP_COMMIT();
        __syncthreads();
    }

    float rsr[2][2];
    #pragma unroll
    for (int mt = 0; mt < 2; mt++)
        #pragma unroll
        for (int h = 0; h < 2; h++)
            rsr[mt][h] = rsqrtf(g_ssq2[m0 + mw + mt*16 + g + h*8] * (1.0f/512.0f) + 1e-6f);

    #pragma unroll
    for (int mt = 0; mt < 2; mt++)
        #pragma unroll
        for (int nt = 0; nt < 4; nt++) {
            int c0 = n0 + nw + nt*8 + tg*2;
            #pragma unroll
            for (int h = 0; h < 2; h++) {
                int r = m0 + mw + mt*16 + g + h*8;
                float rs = rsr[mt][h];
                #pragma unroll
                for (int w2 = 0; w2 < 2; w2++) {
                    float gg = accg[mt][nt][h*2 + w2] * rs;
                    float uu = accu[mt][nt][h*2 + w2] * rs;
                    float hv = (gg / (1.0f + expf(-gg))) * uu;
                    g_hbuf[(size_t)r*N + c0 + w2] = rnd32(hv);
                }
            }
        }
}

// ---------------- attention pass A ----------------
__global__ __launch_bounds__(256) void attn_passA() {
    int c  = blockIdx.x % NC;
    int bh = blockIdx.x / NC;
    int b = bh / H_, h = bh % H_;
    __shared__ float Ks[CC][HD_+4];
    __shared__ float Vs[CC][HD_+4];
    __shared__ float Ws[CC];
    int tid = threadIdx.x;
    #pragma unroll
    for (int r = 0; r < 2; r++) {
        int idx = tid + r*256;
        int t = idx >> 4, d4 = (idx & 15) * 4;
        size_t gbase = (size_t)(b*S_ + c*CC + t)*HID_ + h*HD_ + d4;
        *(float4*)&Ks[t][d4] = *(const float4*)(g_k + gbase);
        *(float4*)&Vs[t][d4] = *(const float4*)(g_v + gbase);
    }
    if (tid < 32) {
        float lg = g_Lg[(b*NC + c)*CC + tid];
        float P  = g_chunkP2[b*NC + c];
        Ws[tid] = P / lg;
    }
    __syncthreads();
    int tx = tid & 15, ty = tid >> 4;
    float acc[4][4] = {};
    #pragma unroll 8
    for (int i = 0; i < CC; i++) {
        float w = Ws[i];
        float4 av = *(const float4*)&Vs[i][ty*4];
        float4 bv = *(const float4*)&Ks[i][tx*4];
        float a[4] = {w*av.x, w*av.y, w*av.z, w*av.w};
        float bb[4] = {bv.x, bv.y, bv.z, bv.w};
        #pragma unroll
        for (int x = 0; x < 4; x++)
            #pragma unroll
            for (int y = 0; y < 4; y++)
                acc[x][y] = fmaf(a[x], bb[y], acc[x][y]);
    }
    float* Sp = g_Schunk + (size_t)(bh*NC + c)*HD_*HD_;
    #pragma unroll
    for (int x = 0; x < 4; x++) {
        float4 o4 = {acc[x][0], acc[x][1], acc[x][2], acc[x][3]};
        *(float4*)(Sp + (ty*4 + x)*HD_ + tx*4) = o4;
    }
}

// ---------------- attention pass B: parallel scan ----------------
__global__ __launch_bounds__(256) void attn_passB(const float* __restrict__ carry,
                                                  float* __restrict__ carry_out) {
    int e  = blockIdx.x * 256 + threadIdx.x;
    int bh = e >> 12;
    int idx = e & 4095;
    const float* Sc = g_Schunk + (size_t)bh*NC*4096 + idx;
    float*       So = g_Sstart + (size_t)bh*NC*4096 + idx;
    int b = bh >> 3;
    float sc[NC], pp[NC];
    #pragma unroll
    for (int c = 0; c < NC; c++) sc[c] = Sc[c*4096];
    #pragma unroll
    for (int c = 0; c < NC; c++) pp[c] = __ldg(&g_chunkP2[b*NC + c]);
    float st = carry[e];
    #pragma unroll
    for (int c = 0; c < NC; c++) {
        So[c*4096] = st;
        st = st * pp[c] + sc[c];
    }
    carry_out[e] = st;
}

// ---------------- attention pass C (+ fused ssqA atomics) ----------------
__global__ __launch_bounds__(256) void attn_passC() {
    int c  = blockIdx.x % NC;
    int bh = blockIdx.x / NC;
    int b = bh / H_, h = bh % H_;
    __shared__ float Qs [CC][HD_+4];
    __shared__ float KVs[CC][HD_+4];
    __shared__ float SsT[HD_][HD_+4];
    __shared__ float Gs [CC][CC+1];
    __shared__ float Lg [CC];
    int tid = threadIdx.x;
    #pragma unroll
    for (int r = 0; r < 2; r++) {
        int idx = tid + r*256;
        int t = idx >> 4, d4 = (idx & 15) * 4;
        size_t gbase = (size_t)(b*S_ + c*CC + t)*HID_ + h*HD_ + d4;
        *(float4*)&Qs[t][d4]  = *(const float4*)(g_q + gbase);
        *(float4*)&KVs[t][d4] = *(const float4*)(g_k + gbase);
    }
    const float* Sp = g_Sstart + (size_t)(bh*NC + c)*4096;
    #pragma unroll
    for (int r = 0; r < 4; r++) {
        int idx = tid + r*256;
        int row = idx >> 4, c4 = (idx & 15) * 4;
        float4 sv = *(const float4*)(Sp + row*HD_ + c4);
        SsT[c4+0][row] = sv.x; SsT[c4+1][row] = sv.y;
        SsT[c4+2][row] = sv.z; SsT[c4+3][row] = sv.w;
    }
    if (tid < 32) Lg[tid] = g_Lg[(b*NC + c)*CC + tid];
    __syncthreads();
    #pragma unroll
    for (int r = 0; r < 4; r++) {
        int e = tid + r*256;
        int t = e >> 5, i = e & 31;
        float gacc = 0.0f;
        if (i <= t) {
            #pragma unroll
            for (int d4 = 0; d4 < HD_; d4 += 4) {
                float4 qv = *(const float4*)&Qs[t][d4];
                float4 kv = *(const float4*)&KVs[i][d4];
                gacc += qv.x*kv.x + qv.y*kv.y + qv.z*kv.z + qv.w*kv.w;
            }
            gacc *= Lg[t] / Lg[i];
        }
        Gs[t][i] = gacc;
    }
    __syncthreads();
    #pragma unroll
    for (int r = 0; r < 2; r++) {
        int idx = tid + r*256;
        int t = idx >> 4, d4 = (idx & 15) * 4;
        *(float4*)&KVs[t][d4] =
            *(const float4*)(g_v + (size_t)(b*S_ + c*CC + t)*HID_ + h*HD_ + d4);
    }
    __syncthreads();
    int t  = tid >> 3;
    int a0 = (tid & 7) * 8;
    float acc[8] = {};
    #pragma unroll 8
    for (int bb = 0; bb < HD_; bb++) {
        float qv = Qs[t][bb];
        float4 s0 = *(const float4*)&SsT[bb][a0];
        float4 s1 = *(const float4*)&SsT[bb][a0+4];
        acc[0] = fmaf(s0.x, qv, acc[0]); acc[1] = fmaf(s0.y, qv, acc[1]);
        acc[2] = fmaf(s0.z, qv, acc[2]); acc[3] = fmaf(s0.w, qv, acc[3]);
        acc[4] = fmaf(s1.x, qv, acc[4]); acc[5] = fmaf(s1.y, qv, acc[5]);
        acc[6] = fmaf(s1.z, qv, acc[6]); acc[7] = fmaf(s1.w, qv, acc[7]);
    }
    float lt = Lg[t];
    #pragma unroll
    for (int j = 0; j < 8; j++) acc[j] *= lt;
    #pragma unroll 8
    for (int i = 0; i < CC; i++) {
        float gg = Gs[t][i];
        float4 v0 = *(const float4*)&KVs[i][a0];
        float4 v1 = *(const float4*)&KVs[i][a0+4];
        acc[0] = fmaf(gg, v0.x, acc[0]); acc[1] = fmaf(gg, v0.y, acc[1]);
        acc[2] = fmaf(gg, v0.z, acc[2]); acc[3] = fmaf(gg, v0.w, acc[3]);
        acc[4] = fmaf(gg, v1.x, acc[4]); acc[5] = fmaf(gg, v1.y, acc[5]);
        acc[6] = fmaf(gg, v1.z, acc[6]); acc[7] = fmaf(gg, v1.w, acc[7]);
    }
    float* op = g_attn + (size_t)(b*S_ + c*CC + t)*HID_ + h*HD_ + a0;
    float4 o0 = {acc[0], acc[1], acc[2], acc[3]};
    float4 o1 = {acc[4], acc[5], acc[6], acc[7]};
    *(float4*)op = o0;
    *(float4*)(op + 4) = o1;
    float ls = acc[0]*acc[0] + acc[1]*acc[1] + acc[2]*acc[2] + acc[3]*acc[3]
             + acc[4]*acc[4] + acc[5]*acc[5] + acc[6]*acc[6] + acc[7]*acc[7];
    #pragma unroll
    for (int o = 1; o < 8; o <<= 1) ls += __shfl_xor_sync(0xffffffffu, ls, o);
    if ((tid & 7) == 0) atomicAdd(&g_ssqA[b*S_ + c*CC + t], ls);
}

// ---------------- host launcher ----------------
extern "C" void kernel_launch(void* const* d_in, const int* in_sizes, int n_in,
                              void* d_out, int out_size) {
    const float* inputs  = (const float*)d_in[0];
    const float* mask    = (const float*)d_in[1];
    const float* carry   = (const float*)d_in[2];
    const float* ln1     = (const float*)d_in[3];
    const float* Wq      = (const float*)d_in[4];
    const float* Wk      = (const float*)d_in[5];
    const float* Wv      = (const float*)d_in[6];
    const float* attn_ln = (const float*)d_in[7];
    const float* Wo      = (const float*)d_in[8];
    const float* bo      = (const float*)d_in[9];
    const float* ln2     = (const float*)d_in[10];
    const float* Wg      = (const float*)d_in[11];
    const float* Wu      = (const float*)d_in[12];
    const float* Wd      = (const float*)d_in[13];

    float* out        = (float*)d_out;
    float* out_carry  = out;
    float* out_x      = out + B_*H_*HD_*HD_;

    float *p_attn, *p_y1, *p_hbuf, *p_wo, *p_wd, *p_r1, *p_ssqA, *p_ssq2;
    cudaGetSymbolAddress((void**)&p_attn,  g_attn);
    cudaGetSymbolAddress((void**)&p_y1,    g_y1);
    cudaGetSymbolAddress((void**)&p_hbuf,  g_hbuf);
    cudaGetSymbolAddress((void**)&p_wo,    g_wo);
    cudaGetSymbolAddress((void**)&p_wd,    g_wd);
    cudaGetSymbolAddress((void**)&p_r1,    g_r1);
    cudaGetSymbolAddress((void**)&p_ssqA,  g_ssqA);
    cudaGetSymbolAddress((void**)&p_ssq2,  g_ssq2);

    const int smem_s   = 4*(64*36 + 64*36)*4;            // 73728
    const int smem_qkv = 3*(128*36 + 64*36)*4;           // 82944
    const int smem_gu  = 3*(128*36 + 2*64*36)*4;         // 110592

    cudaFuncSetAttribute((const void*)gemm_tc<4,4,0>, cudaFuncAttributeMaxDynamicSharedMemorySize, smem_s);
    cudaFuncSetAttribute((const void*)gemm_tc<2,4,1>, cudaFuncAttributeMaxDynamicSharedMemorySize, smem_s);
    cudaFuncSetAttribute((const void*)gemm_qkv_tc,    cudaFuncAttributeMaxDynamicSharedMemorySize, smem_qkv);
    cudaFuncSetAttribute((const void*)gemm_gu_tc,     cudaFuncAttributeMaxDynamicSharedMemorySize, smem_gu);

    // 1. prep: weight transpose (ln folded) + r1 + decay scan + ssq zero
    prep_all<<<4225, dim3(32, 8)>>>(Wq, Wk, Wv, Wo, Wg, Wu, Wd,
                                    inputs, ln1, attn_ln, ln2, mask, p_r1);
    // 2. q,k,v from raw inputs
    gemm_qkv_tc<<<dim3(24, 8), 256, smem_qkv>>>(inputs);
    // 3-5. chunked linear attention (passC also accumulates ssqA)
    attn_passA<<<B_*H_*NC, 256>>>();
    attn_passB<<<256, 256>>>(carry, out_carry);
    attn_passC<<<B_*H_*NC, 256>>>();
    // 6. y1 = rsA*(attn @ wo') + bo + inputs; ssq2 += y1^2; out_x = y1
    gemm_tc<2, 4, 1><<<dim3(8, 16), 256, smem_s>>>(p_attn, p_wo, p_y1,
                                                   512, 512, 512, 512, 0,
                                                   bo, inputs, p_ssqA, p_ssq2, out_x);
    // 7. h = silu(rs2*(y1@wg')) * (rs2*(y1@wu'))
    gemm_gu_tc<<<dim3(32, 8), 256, smem_gu>>>(p_y1);
    // 8. Wd split-K=4: atomicAdd partials directly onto out_x (pre-filled with y1)
    gemm_tc<4, 4, 0><<<dim3(8, 16, 4), 256, smem_s>>>(p_hbuf, p_wd, out_x,
                                                      512, 512, 2048, 2048, 512,
                                                      nullptr, nullptr, nullptr,
                                                      nullptr, nullptr);
}